// round 3
// baseline (speedup 1.0000x reference)
#include <cuda_runtime.h>

// Fixed shapes: z_e [16,2048,512] -> N=32768 rows, codebook [4096,512]
#define NROWS 32768
#define DIM   512
#define KC    4096

// Scratch (no allocations allowed -> __device__ globals)
__device__ float g_wnorm[KC];
__device__ float g_xnorm[NROWS];
__device__ int   g_k[NROWS];
__device__ float g_partial[NROWS];
__device__ int   g_used[KC];

// ---------------------------------------------------------------------------
__global__ void init_kernel() {
    int i = blockIdx.x * blockDim.x + threadIdx.x;
    if (i < KC) g_used[i] = 0;
}

// ---------------------------------------------------------------------------
// ||w||^2 per code: sequential scalar reduce, acc = fl(acc + fl(w*w)), no fma.
__global__ void wnorm_kernel(const float* __restrict__ cb) {
    int code = blockIdx.x * blockDim.x + threadIdx.x;
    if (code >= KC) return;
    const float* p = cb + (size_t)code * DIM;
    float acc = 0.f;
    for (int d = 0; d < DIM; d++)
        acc = __fadd_rn(acc, __fmul_rn(p[d], p[d]));
    g_wnorm[code] = acc;
}

// ||x||^2 per row, same sequential no-fma order.
__global__ void xnorm_kernel(const float* __restrict__ z) {
    int row = blockIdx.x * blockDim.x + threadIdx.x;
    if (row >= NROWS) return;
    const float* p = z + (size_t)row * DIM;
    float acc = 0.f;
    for (int d = 0; d < DIM; d++)
        acc = __fadd_rn(acc, __fmul_rn(p[d], p[d]));
    g_xnorm[row] = acc;
}

// ---------------------------------------------------------------------------
// Packed f32x2 helpers. Each 32-bit half of a b64 is an INDEPENDENT IEEE fp32
// FMA — per-chain rounding order is identical to scalar __fmaf_rn chains.
__device__ __forceinline__ unsigned long long dup2(float a) {
    unsigned long long r;
    asm("mov.b64 %0, {%1, %1};" : "=l"(r) : "f"(a));
    return r;
}
__device__ __forceinline__ void fma2(unsigned long long& d,
                                     unsigned long long a,
                                     unsigned long long b) {
    asm("fma.rn.f32x2 %0, %1, %2, %0;" : "+l"(d) : "l"(a), "l"(b));
}
union U64F2 { unsigned long long u; float2 f; };

// ---------------------------------------------------------------------------
// Fused fp32 GEMM + argmin. dot = single ascending-k FMA chain per (row,code)
// (bit-identical to round-2 pass), executed 2 chains/instruction via f32x2.
// Score: d = fl( fl(xnorm - fl(2*dot)) + wnorm ); argmin strict <, asc index.
#define BM 128
#define BN 128
#define BK 16
#define TM 8
#define TN 8

__global__ void __launch_bounds__(256, 2)
vq_argmin_kernel(const float* __restrict__ A, const float* __restrict__ B) {
    __shared__ float As[BK][BM];
    __shared__ float Bs[BK][BN];
    __shared__ float s_val[BM][17];
    __shared__ int   s_idx[BM][17];

    const int tid = threadIdx.x;
    const int tx  = tid & 15;   // col group (8 codes)
    const int ty  = tid >> 4;   // row group (8 rows)
    const int rowBase = blockIdx.x * BM;

    float bestV = 3.4e38f;
    int   bestI = 0;

    for (int cbase = 0; cbase < KC; cbase += BN) {
        unsigned long long acc[TM][TN / 2];   // [i][jj] = (acc[i][2jj], acc[i][2jj+1])
        #pragma unroll
        for (int i = 0; i < TM; i++)
            #pragma unroll
            for (int jj = 0; jj < TN / 2; jj++) acc[i][jj] = 0ull;

        for (int dk = 0; dk < DIM; dk += BK) {
            #pragma unroll
            for (int t = 0; t < 2; t++) {
                int s  = tid + t * 256;
                int m  = s >> 2;
                int c4 = (s & 3) * 4;
                float4 v = *reinterpret_cast<const float4*>(
                    &A[(size_t)(rowBase + m) * DIM + dk + c4]);
                As[c4 + 0][m] = v.x; As[c4 + 1][m] = v.y;
                As[c4 + 2][m] = v.z; As[c4 + 3][m] = v.w;
            }
            #pragma unroll
            for (int t = 0; t < 2; t++) {
                int s  = tid + t * 256;
                int n  = s >> 2;
                int c4 = (s & 3) * 4;
                float4 v = *reinterpret_cast<const float4*>(
                    &B[(size_t)(cbase + n) * DIM + dk + c4]);
                Bs[c4 + 0][n] = v.x; Bs[c4 + 1][n] = v.y;
                Bs[c4 + 2][n] = v.z; Bs[c4 + 3][n] = v.w;
            }
            __syncthreads();

            #pragma unroll
            for (int kk = 0; kk < BK; kk++) {
                float a[TM];
                *(float4*)&a[0] = *(const float4*)&As[kk][ty * TM];
                *(float4*)&a[4] = *(const float4*)&As[kk][ty * TM + 4];
                // b pairs come pre-packed from 128-bit shared loads:
                // u64 low word = Bs[kk][tx*8+2jj], high = +2jj+1 (little-endian)
                ulonglong2 b01 = *(const ulonglong2*)&Bs[kk][tx * TN];
                ulonglong2 b23 = *(const ulonglong2*)&Bs[kk][tx * TN + 4];
                unsigned long long bq[4] = { b01.x, b01.y, b23.x, b23.y };
                #pragma unroll
                for (int i = 0; i < TM; i++) {
                    unsigned long long ad = dup2(a[i]);
                    #pragma unroll
                    for (int jj = 0; jj < TN / 2; jj++)
                        fma2(acc[i][jj], ad, bq[jj]);
                }
            }
            __syncthreads();
        }

        // per-thread argmin over its 8 codes, reference rounding order,
        // ascending column index (j = 2*jj + h)
        #pragma unroll
        for (int i = 0; i < TM; i++) {
            float xn = g_xnorm[rowBase + ty * TM + i];
            float mv = 3.4e38f; int mi = 0;
            #pragma unroll
            for (int jj = 0; jj < TN / 2; jj++) {
                U64F2 u; u.u = acc[i][jj];
                float av[2] = { u.f.x, u.f.y };
                #pragma unroll
                for (int h = 0; h < 2; h++) {
                    int   col = cbase + tx * TN + 2 * jj + h;
                    float p   = __fmul_rn(2.0f, av[h]);
                    float q   = __fsub_rn(xn, p);
                    float sc  = __fadd_rn(q, g_wnorm[col]);
                    if (sc < mv) { mv = sc; mi = col; }
                }
            }
            s_val[ty * TM + i][tx] = mv;
            s_idx[ty * TM + i][tx] = mi;
        }
        __syncthreads();

        // merge across the 16 col-groups (ascending tx => ascending index)
        if (tid < BM) {
            #pragma unroll
            for (int j = 0; j < 16; j++) {
                float v = s_val[tid][j];
                if (v < bestV) { bestV = v; bestI = s_idx[tid][j]; }
            }
        }
        __syncthreads();
    }

    if (tid < BM) g_k[rowBase + tid] = bestI;
}

// ---------------------------------------------------------------------------
// Gather z_q, emit straight-through output x + (z_q - x) (same fp ops as JAX),
// per-row loss partial, used flags, and k as float.
__global__ void gather_kernel(const float* __restrict__ z,
                              const float* __restrict__ cb,
                              float* __restrict__ out) {
    __shared__ float red[128];
    int row = blockIdx.x;
    int t   = threadIdx.x;
    int k   = g_k[row];

    float4 w = reinterpret_cast<const float4*>(cb + (size_t)k   * DIM)[t];
    float4 x = reinterpret_cast<const float4*>(z  + (size_t)row * DIM)[t];

    float4 o;
    o.x = __fadd_rn(x.x, __fsub_rn(w.x, x.x));
    o.y = __fadd_rn(x.y, __fsub_rn(w.y, x.y));
    o.z = __fadd_rn(x.z, __fsub_rn(w.z, x.z));
    o.w = __fadd_rn(x.w, __fsub_rn(w.w, x.w));
    reinterpret_cast<float4*>(out + (size_t)row * DIM)[t] = o;

    float dx = __fsub_rn(x.x, w.x), dy = __fsub_rn(x.y, w.y);
    float dz = __fsub_rn(x.z, w.z), dw = __fsub_rn(x.w, w.w);
    red[t] = dx * dx + dy * dy + dz * dz + dw * dw;
    __syncthreads();
    #pragma unroll
    for (int off = 64; off > 0; off >>= 1) {
        if (t < off) red[t] += red[t + off];
        __syncthreads();
    }
    if (t == 0) {
        g_partial[row] = red[0];
        g_used[k] = 1;
        out[(size_t)NROWS * DIM + row] = (float)k;   // k segment
    }
}

// ---------------------------------------------------------------------------
__global__ void finalize_kernel(float* __restrict__ out) {
    __shared__ double red[1024];
    int t = threadIdx.x;

    double s = 0.0;
    for (int i = t; i < NROWS; i += 1024) s += (double)g_partial[i];
    red[t] = s;
    __syncthreads();
    #pragma unroll
    for (int off = 512; off > 0; off >>= 1) {
        if (t < off) red[t] += red[t + off];
        __syncthreads();
    }
    double lossTotal = red[0];
    __syncthreads();

    double u = 0.0;
    for (int i = t; i < KC; i += 1024) u += (double)g_used[i];
    red[t] = u;
    __syncthreads();
    #pragma unroll
    for (int off = 512; off > 0; off >>= 1) {
        if (t < off) red[t] += red[t + off];
        __syncthreads();
    }

    if (t == 0) {
        size_t base = (size_t)NROWS * DIM + NROWS;
        out[base]     = (float)(0.25 * lossTotal / ((double)NROWS * (double)DIM));
        out[base + 1] = (float)(red[0] / (double)KC);
    }
}

// ---------------------------------------------------------------------------
extern "C" void kernel_launch(void* const* d_in, const int* in_sizes, int n_in,
                              void* d_out, int out_size) {
    const float* z  = (const float*)d_in[0];   // z_e [32768, 512]
    const float* cb = (const float*)d_in[1];   // codebook [4096, 512]
    if (in_sizes[0] == KC * DIM) {             // defensive: swap if order differs
        z  = (const float*)d_in[1];
        cb = (const float*)d_in[0];
    }
    float* out = (float*)d_out;                // [z_q_st | k | vq_loss | utilization]

    init_kernel<<<(KC + 255) / 256, 256>>>();
    wnorm_kernel<<<KC / 256, 256>>>(cb);
    xnorm_kernel<<<NROWS / 256, 256>>>(z);
    vq_argmin_kernel<<<NROWS / BM, 256>>>(z, cb);
    gather_kernel<<<NROWS, 128>>>(z, cb, out);
    finalize_kernel<<<1, 1024>>>(out);
}

// round 4
// speedup vs baseline: 1.1720x; 1.1720x over previous
#include <cuda_runtime.h>

// Fixed shapes: z_e [16,2048,512] -> N=32768 rows, codebook [4096,512]
#define NROWS 32768
#define DIM   512
#define KC    4096

__device__ float g_wnorm[KC];
__device__ float g_xnorm[NROWS];
__device__ int   g_k[NROWS];
__device__ float g_partial[NROWS];
__device__ int   g_used[KC];

// ---------------------------------------------------------------------------
__global__ void init_kernel() {
    int i = blockIdx.x * blockDim.x + threadIdx.x;
    if (i < KC) g_used[i] = 0;
}

// ---------------------------------------------------------------------------
// ||w||^2 / ||x||^2: sequential scalar reduce, acc = fl(acc + fl(v*v)), no fma.
__global__ void wnorm_kernel(const float* __restrict__ cb) {
    int code = blockIdx.x * blockDim.x + threadIdx.x;
    if (code >= KC) return;
    const float* p = cb + (size_t)code * DIM;
    float acc = 0.f;
    for (int d = 0; d < DIM; d++)
        acc = __fadd_rn(acc, __fmul_rn(p[d], p[d]));
    g_wnorm[code] = acc;
}

__global__ void xnorm_kernel(const float* __restrict__ z) {
    int row = blockIdx.x * blockDim.x + threadIdx.x;
    if (row >= NROWS) return;
    const float* p = z + (size_t)row * DIM;
    float acc = 0.f;
    for (int d = 0; d < DIM; d++)
        acc = __fadd_rn(acc, __fmul_rn(p[d], p[d]));
    g_xnorm[row] = acc;
}

// ---------------------------------------------------------------------------
// Packed f32x2: each 32-bit half is an independent IEEE fp32 FMA chain.
__device__ __forceinline__ unsigned long long dup2(float a) {
    unsigned long long r;
    asm("mov.b64 %0, {%1, %1};" : "=l"(r) : "f"(a));
    return r;
}
__device__ __forceinline__ void fma2(unsigned long long& d,
                                     unsigned long long a,
                                     unsigned long long b) {
    asm("fma.rn.f32x2 %0, %1, %2, %0;" : "+l"(d) : "l"(a), "l"(b));
}
union U64F2 { unsigned long long u; float2 f; };

// ---------------------------------------------------------------------------
// Fused fp32 GEMM + argmin.
//  - dot per (row,code): single ascending-k FMA chain (bit-identical to the
//    round-2 passing kernel), 2 chains per fma.rn.f32x2.
//  - score: d = fl( fl(xnorm - fl(2*dot)) + wnorm )
//  - argmin: (value, index) comparator == jnp.argmin first-occurrence.
// Tile: BM=64 rows x BN=256 codes, BK=16, 128 threads, TM=8 x TN=16/thread.
// Thread's 16 cols = quads {tx+16j}, j=0..3 -> conflict-free B LDS.128 reads.
#define BM 64
#define BN 256
#define BK 16
#define TM 8
#define AMS 68    // As row stride (floats), padded: 2-way store conflicts max
#define BNS 260   // Bs row stride (floats), padded, 16B-aligned

__global__ void __launch_bounds__(128, 2)
vq_argmin_kernel(const float* __restrict__ A, const float* __restrict__ B) {
    __shared__ float As[BK * AMS];
    __shared__ float Bs[BK * BNS];
    __shared__ float s_val[BM][17];
    __shared__ int   s_idx[BM][17];

    const int tid = threadIdx.x;
    const int tx  = tid & 15;    // col group
    const int ty  = tid >> 4;    // row group (0..7)
    const int rowBase = blockIdx.x * BM;

    float bestV = 3.4e38f;
    int   bestI = 0x7fffffff;

    for (int cbase = 0; cbase < KC; cbase += BN) {
        // acc[i][2j+h] halves cover cols 4*(tx+16j) + 2h + {0,1}
        unsigned long long acc[TM][8];
        #pragma unroll
        for (int i = 0; i < TM; i++)
            #pragma unroll
            for (int p = 0; p < 8; p++) acc[i][p] = 0ull;

        for (int dk = 0; dk < DIM; dk += BK) {
            // A tile: 64 rows x 16 dims -> As[k][m] (transposed)
            #pragma unroll
            for (int t = 0; t < 2; t++) {
                int s  = tid + t * 128;
                int m  = s >> 2;
                int c4 = (s & 3) * 4;
                float4 v = *reinterpret_cast<const float4*>(
                    &A[(size_t)(rowBase + m) * DIM + dk + c4]);
                As[(c4 + 0) * AMS + m] = v.x;
                As[(c4 + 1) * AMS + m] = v.y;
                As[(c4 + 2) * AMS + m] = v.z;
                As[(c4 + 3) * AMS + m] = v.w;
            }
            // B tile: 256 codes x 16 dims -> Bs[k][n] (transposed)
            #pragma unroll
            for (int t = 0; t < 8; t++) {
                int s  = tid + t * 128;
                int n  = s >> 2;
                int c4 = (s & 3) * 4;
                float4 v = *reinterpret_cast<const float4*>(
                    &B[(size_t)(cbase + n) * DIM + dk + c4]);
                Bs[(c4 + 0) * BNS + n] = v.x;
                Bs[(c4 + 1) * BNS + n] = v.y;
                Bs[(c4 + 2) * BNS + n] = v.z;
                Bs[(c4 + 3) * BNS + n] = v.w;
            }
            __syncthreads();

            #pragma unroll
            for (int kk = 0; kk < BK; kk++) {
                float a[TM];
                *(float4*)&a[0] = *(const float4*)&As[kk * AMS + ty * TM];
                *(float4*)&a[4] = *(const float4*)&As[kk * AMS + ty * TM + 4];
                unsigned long long bq[8];
                #pragma unroll
                for (int j = 0; j < 4; j++) {
                    ulonglong2 b = *(const ulonglong2*)
                        &Bs[kk * BNS + 4 * (tx + 16 * j)];
                    bq[2 * j]     = b.x;
                    bq[2 * j + 1] = b.y;
                }
                #pragma unroll
                for (int i = 0; i < TM; i++) {
                    unsigned long long ad = dup2(a[i]);
                    #pragma unroll
                    for (int p = 0; p < 8; p++)
                        fma2(acc[i][p], ad, bq[p]);
                }
            }
            __syncthreads();
        }

        // per-thread argmin over its 16 cols, reference rounding order,
        // (value,index) comparator -> order-independent first-occurrence
        #pragma unroll
        for (int i = 0; i < TM; i++) {
            float xn = g_xnorm[rowBase + ty * TM + i];
            float mv = 3.4e38f; int mi = 0x7fffffff;
            #pragma unroll
            for (int j = 0; j < 4; j++) {
                #pragma unroll
                for (int h = 0; h < 2; h++) {
                    U64F2 u; u.u = acc[i][2 * j + h];
                    int c0 = cbase + 4 * (tx + 16 * j) + 2 * h;
                    float av[2] = { u.f.x, u.f.y };
                    #pragma unroll
                    for (int e = 0; e < 2; e++) {
                        int   col = c0 + e;
                        float p   = __fmul_rn(2.0f, av[e]);
                        float q   = __fsub_rn(xn, p);
                        float sc  = __fadd_rn(q, g_wnorm[col]);
                        if (sc < mv || (sc == mv && col < mi)) { mv = sc; mi = col; }
                    }
                }
            }
            s_val[ty * TM + i][tx] = mv;
            s_idx[ty * TM + i][tx] = mi;
        }
        __syncthreads();

        if (tid < BM) {
            #pragma unroll
            for (int j = 0; j < 16; j++) {
                float v = s_val[tid][j];
                int   ix = s_idx[tid][j];
                if (v < bestV || (v == bestV && ix < bestI)) { bestV = v; bestI = ix; }
            }
        }
        __syncthreads();
    }

    if (tid < BM) g_k[rowBase + tid] = bestI;
}

// ---------------------------------------------------------------------------
// Gather z_q, ST output x + (z_q - x) (same fp ops as JAX), loss partials,
// used flags, k as float.
__global__ void gather_kernel(const float* __restrict__ z,
                              const float* __restrict__ cb,
                              float* __restrict__ out) {
    __shared__ float red[128];
    int row = blockIdx.x;
    int t   = threadIdx.x;
    int k   = g_k[row];

    float4 w = reinterpret_cast<const float4*>(cb + (size_t)k   * DIM)[t];
    float4 x = reinterpret_cast<const float4*>(z  + (size_t)row * DIM)[t];

    float4 o;
    o.x = __fadd_rn(x.x, __fsub_rn(w.x, x.x));
    o.y = __fadd_rn(x.y, __fsub_rn(w.y, x.y));
    o.z = __fadd_rn(x.z, __fsub_rn(w.z, x.z));
    o.w = __fadd_rn(x.w, __fsub_rn(w.w, x.w));
    reinterpret_cast<float4*>(out + (size_t)row * DIM)[t] = o;

    float dx = __fsub_rn(x.x, w.x), dy = __fsub_rn(x.y, w.y);
    float dz = __fsub_rn(x.z, w.z), dw = __fsub_rn(x.w, w.w);
    red[t] = dx * dx + dy * dy + dz * dz + dw * dw;
    __syncthreads();
    #pragma unroll
    for (int off = 64; off > 0; off >>= 1) {
        if (t < off) red[t] += red[t + off];
        __syncthreads();
    }
    if (t == 0) {
        g_partial[row] = red[0];
        g_used[k] = 1;
        out[(size_t)NROWS * DIM + row] = (float)k;   // k segment
    }
}

// ---------------------------------------------------------------------------
__global__ void finalize_kernel(float* __restrict__ out) {
    __shared__ double red[1024];
    int t = threadIdx.x;

    double s = 0.0;
    for (int i = t; i < NROWS; i += 1024) s += (double)g_partial[i];
    red[t] = s;
    __syncthreads();
    #pragma unroll
    for (int off = 512; off > 0; off >>= 1) {
        if (t < off) red[t] += red[t + off];
        __syncthreads();
    }
    double lossTotal = red[0];
    __syncthreads();

    double u = 0.0;
    for (int i = t; i < KC; i += 1024) u += (double)g_used[i];
    red[t] = u;
    __syncthreads();
    #pragma unroll
    for (int off = 512; off > 0; off >>= 1) {
        if (t < off) red[t] += red[t + off];
        __syncthreads();
    }

    if (t == 0) {
        size_t base = (size_t)NROWS * DIM + NROWS;
        out[base]     = (float)(0.25 * lossTotal / ((double)NROWS * (double)DIM));
        out[base + 1] = (float)(red[0] / (double)KC);
    }
}

// ---------------------------------------------------------------------------
extern "C" void kernel_launch(void* const* d_in, const int* in_sizes, int n_in,
                              void* d_out, int out_size) {
    const float* z  = (const float*)d_in[0];   // z_e [32768, 512]
    const float* cb = (const float*)d_in[1];   // codebook [4096, 512]
    if (in_sizes[0] == KC * DIM) {             // defensive: swap if order differs
        z  = (const float*)d_in[1];
        cb = (const float*)d_in[0];
    }
    float* out = (float*)d_out;                // [z_q_st | k | vq_loss | utilization]

    init_kernel<<<(KC + 255) / 256, 256>>>();
    wnorm_kernel<<<KC / 256, 256>>>(cb);
    xnorm_kernel<<<NROWS / 256, 256>>>(z);
    vq_argmin_kernel<<<NROWS / BM, 128>>>(z, cb);
    gather_kernel<<<NROWS, 128>>>(z, cb, out);
    finalize_kernel<<<1, 1024>>>(out);
}

// round 5
// speedup vs baseline: 1.3502x; 1.1520x over previous
#include <cuda_runtime.h>
#include <cstdint>

// Fixed shapes: z_e [16,2048,512] -> N=32768 rows, codebook [4096,512]
#define NROWS 32768
#define DIM   512
#define KC    4096

__device__ float g_wnorm[KC];
__device__ float g_xnorm[NROWS];
__device__ int   g_k[NROWS];
__device__ float g_partial[NROWS];
__device__ int   g_used[KC];
// k-major transposed operands (sanctioned static scratch)
__device__ float g_AT[DIM * NROWS];   // AT[d][m] = z[m][d]      (64 MB)
__device__ float g_BT[DIM * KC];      // BT[d][n] = cb[n][d]     ( 8 MB)

// ---------------------------------------------------------------------------
__global__ void init_kernel() {
    int i = blockIdx.x * blockDim.x + threadIdx.x;
    if (i < KC) g_used[i] = 0;
}

// ---------------------------------------------------------------------------
// ||w||^2 / ||x||^2: sequential scalar reduce, acc = fl(acc + fl(v*v)), no fma.
__global__ void wnorm_kernel(const float* __restrict__ cb) {
    int code = blockIdx.x * blockDim.x + threadIdx.x;
    if (code >= KC) return;
    const float* p = cb + (size_t)code * DIM;
    float acc = 0.f;
    for (int d = 0; d < DIM; d++)
        acc = __fadd_rn(acc, __fmul_rn(p[d], p[d]));
    g_wnorm[code] = acc;
}

__global__ void xnorm_kernel(const float* __restrict__ z) {
    int row = blockIdx.x * blockDim.x + threadIdx.x;
    if (row >= NROWS) return;
    const float* p = z + (size_t)row * DIM;
    float acc = 0.f;
    for (int d = 0; d < DIM; d++)
        acc = __fadd_rn(acc, __fmul_rn(p[d], p[d]));
    g_xnorm[row] = acc;
}

// ---------------------------------------------------------------------------
// Tiled transposes: in[R][C] -> out[C][R]
__global__ void transposeA_kernel(const float* __restrict__ in) {
    __shared__ float tile[32][33];
    int c0 = blockIdx.x * 32, r0 = blockIdx.y * 32;
    #pragma unroll
    for (int i = threadIdx.y; i < 32; i += 8)
        tile[i][threadIdx.x] = in[(size_t)(r0 + i) * DIM + c0 + threadIdx.x];
    __syncthreads();
    #pragma unroll
    for (int i = threadIdx.y; i < 32; i += 8)
        g_AT[(size_t)(c0 + i) * NROWS + r0 + threadIdx.x] = tile[threadIdx.x][i];
}

__global__ void transposeB_kernel(const float* __restrict__ in) {
    __shared__ float tile[32][33];
    int c0 = blockIdx.x * 32, r0 = blockIdx.y * 32;
    #pragma unroll
    for (int i = threadIdx.y; i < 32; i += 8)
        tile[i][threadIdx.x] = in[(size_t)(r0 + i) * DIM + c0 + threadIdx.x];
    __syncthreads();
    #pragma unroll
    for (int i = threadIdx.y; i < 32; i += 8)
        g_BT[(size_t)(c0 + i) * KC + r0 + threadIdx.x] = tile[threadIdx.x][i];
}

// ---------------------------------------------------------------------------
// Packed f32x2: each 32-bit half is an independent IEEE fp32 FMA chain.
__device__ __forceinline__ unsigned long long dup2(float a) {
    unsigned long long r;
    asm("mov.b64 %0, {%1, %1};" : "=l"(r) : "f"(a));
    return r;
}
__device__ __forceinline__ void fma2(unsigned long long& d,
                                     unsigned long long a,
                                     unsigned long long b) {
    asm("fma.rn.f32x2 %0, %1, %2, %0;" : "+l"(d) : "l"(a), "l"(b));
}
union U64F2 { unsigned long long u; float2 f; };

__device__ __forceinline__ void cp16(uint32_t smem, const float* g) {
    asm volatile("cp.async.cg.shared.global [%0], [%1], 16;" :: "r"(smem), "l"(g));
}

// ---------------------------------------------------------------------------
// Fused fp32 GEMM + argmin, cp.async double-buffered from k-major operands.
//  - dot per (row,code): single ascending-k FMA chain, bit-identical to the
//    round-2/3/4 passing kernels (2 chains per fma.rn.f32x2).
//  - score: d = fl( fl(xnorm - fl(2*dot)) + wnorm )
//  - argmin: (value,index) comparator == jnp.argmin first-occurrence.
// Tile: BM=64 x BN=256, BK=16, 128 threads, 8x16 per thread.
#define BM 64
#define BN 256
#define BK 16
#define TM 8

__global__ void __launch_bounds__(128, 2)
vq_argmin_kernel() {
    __shared__ float As[2][BK][BM];    //  8 KB
    __shared__ float Bs[2][BK][BN];    // 32 KB
    __shared__ float s_val[BM][17];
    __shared__ int   s_idx[BM][17];

    const int tid = threadIdx.x;
    const int tx  = tid & 15;    // col group
    const int ty  = tid >> 4;    // row group (0..7)
    const int rowBase = blockIdx.x * BM;

    float bestV = 3.4e38f;
    int   bestI = 0x7fffffff;

    // ---- pipeline helpers -------------------------------------------------
    auto prefetch = [&](int cb, int dk, int b) {
        #pragma unroll
        for (int t = 0; t < 2; t++) {               // A: 256 x 16B ops
            int idx = tid + t * 128;
            int k = idx >> 4, seg = (idx & 15) * 4;
            cp16((uint32_t)__cvta_generic_to_shared(&As[b][k][seg]),
                 &g_AT[(size_t)(dk + k) * NROWS + rowBase + seg]);
        }
        #pragma unroll
        for (int t = 0; t < 8; t++) {               // B: 1024 x 16B ops
            int idx = tid + t * 128;
            int k = idx >> 6, seg = (idx & 63) * 4;
            cp16((uint32_t)__cvta_generic_to_shared(&Bs[b][k][seg]),
                 &g_BT[(size_t)(dk + k) * KC + cb + seg]);
        }
    };

    int buf = 0;
    prefetch(0, 0, 0);
    asm volatile("cp.async.commit_group;");

    for (int cbase = 0; cbase < KC; cbase += BN) {
        unsigned long long acc[TM][8];
        #pragma unroll
        for (int i = 0; i < TM; i++)
            #pragma unroll
            for (int p = 0; p < 8; p++) acc[i][p] = 0ull;

        for (int dk = 0; dk < DIM; dk += BK) {
            // prefetch next stage into the buffer freed by stage s-1
            int ndk = dk + BK, ncb = cbase;
            if (ndk == DIM) { ndk = 0; ncb += BN; }
            if (ncb < KC) prefetch(ncb, ndk, buf ^ 1);
            asm volatile("cp.async.commit_group;");
            asm volatile("cp.async.wait_group 1;");
            __syncthreads();                       // stage s visible to all

            #pragma unroll
            for (int kk = 0; kk < BK; kk++) {
                float a[TM];
                *(float4*)&a[0] = *(const float4*)&As[buf][kk][ty * TM];
                *(float4*)&a[4] = *(const float4*)&As[buf][kk][ty * TM + 4];
                unsigned long long bq[8];
                #pragma unroll
                for (int j = 0; j < 4; j++) {
                    ulonglong2 b = *(const ulonglong2*)&Bs[buf][kk][4 * (tx + 16 * j)];
                    bq[2 * j]     = b.x;
                    bq[2 * j + 1] = b.y;
                }
                #pragma unroll
                for (int i = 0; i < TM; i++) {
                    unsigned long long ad = dup2(a[i]);
                    #pragma unroll
                    for (int p = 0; p < 8; p++)
                        fma2(acc[i][p], ad, bq[p]);
                }
            }
            buf ^= 1;
            __syncthreads();                       // free this buffer
        }

        // per-thread argmin over its 16 cols, reference rounding order
        #pragma unroll
        for (int i = 0; i < TM; i++) {
            float xn = g_xnorm[rowBase + ty * TM + i];
            float mv = 3.4e38f; int mi = 0x7fffffff;
            #pragma unroll
            for (int j = 0; j < 4; j++) {
                #pragma unroll
                for (int h = 0; h < 2; h++) {
                    U64F2 u; u.u = acc[i][2 * j + h];
                    int c0 = cbase + 4 * (tx + 16 * j) + 2 * h;
                    float av[2] = { u.f.x, u.f.y };
                    #pragma unroll
                    for (int e = 0; e < 2; e++) {
                        int   col = c0 + e;
                        float p   = __fmul_rn(2.0f, av[e]);
                        float q   = __fsub_rn(xn, p);
                        float sc  = __fadd_rn(q, g_wnorm[col]);
                        if (sc < mv || (sc == mv && col < mi)) { mv = sc; mi = col; }
                    }
                }
            }
            s_val[ty * TM + i][tx] = mv;
            s_idx[ty * TM + i][tx] = mi;
        }
        __syncthreads();

        if (tid < BM) {
            #pragma unroll
            for (int j = 0; j < 16; j++) {
                float v = s_val[tid][j];
                int  ix = s_idx[tid][j];
                if (v < bestV || (v == bestV && ix < bestI)) { bestV = v; bestI = ix; }
            }
        }
        __syncthreads();
    }

    if (tid < BM) g_k[rowBase + tid] = bestI;
}

// ---------------------------------------------------------------------------
// Gather z_q, ST output x + (z_q - x) (same fp ops as JAX), loss partials,
// used flags, k as float.
__global__ void gather_kernel(const float* __restrict__ z,
                              const float* __restrict__ cb,
                              float* __restrict__ out) {
    __shared__ float red[128];
    int row = blockIdx.x;
    int t   = threadIdx.x;
    int k   = g_k[row];

    float4 w = reinterpret_cast<const float4*>(cb + (size_t)k   * DIM)[t];
    float4 x = reinterpret_cast<const float4*>(z  + (size_t)row * DIM)[t];

    float4 o;
    o.x = __fadd_rn(x.x, __fsub_rn(w.x, x.x));
    o.y = __fadd_rn(x.y, __fsub_rn(w.y, x.y));
    o.z = __fadd_rn(x.z, __fsub_rn(w.z, x.z));
    o.w = __fadd_rn(x.w, __fsub_rn(w.w, x.w));
    reinterpret_cast<float4*>(out + (size_t)row * DIM)[t] = o;

    float dx = __fsub_rn(x.x, w.x), dy = __fsub_rn(x.y, w.y);
    float dz = __fsub_rn(x.z, w.z), dw = __fsub_rn(x.w, w.w);
    red[t] = dx * dx + dy * dy + dz * dz + dw * dw;
    __syncthreads();
    #pragma unroll
    for (int off = 64; off > 0; off >>= 1) {
        if (t < off) red[t] += red[t + off];
        __syncthreads();
    }
    if (t == 0) {
        g_partial[row] = red[0];
        g_used[k] = 1;
        out[(size_t)NROWS * DIM + row] = (float)k;   // k segment
    }
}

// ---------------------------------------------------------------------------
__global__ void finalize_kernel(float* __restrict__ out) {
    __shared__ double red[1024];
    int t = threadIdx.x;

    double s = 0.0;
    for (int i = t; i < NROWS; i += 1024) s += (double)g_partial[i];
    red[t] = s;
    __syncthreads();
    #pragma unroll
    for (int off = 512; off > 0; off >>= 1) {
        if (t < off) red[t] += red[t + off];
        __syncthreads();
    }
    double lossTotal = red[0];
    __syncthreads();

    double u = 0.0;
    for (int i = t; i < KC; i += 1024) u += (double)g_used[i];
    red[t] = u;
    __syncthreads();
    #pragma unroll
    for (int off = 512; off > 0; off >>= 1) {
        if (t < off) red[t] += red[t + off];
        __syncthreads();
    }

    if (t == 0) {
        size_t base = (size_t)NROWS * DIM + NROWS;
        out[base]     = (float)(0.25 * lossTotal / ((double)NROWS * (double)DIM));
        out[base + 1] = (float)(red[0] / (double)KC);
    }
}

// ---------------------------------------------------------------------------
extern "C" void kernel_launch(void* const* d_in, const int* in_sizes, int n_in,
                              void* d_out, int out_size) {
    const float* z  = (const float*)d_in[0];   // z_e [32768, 512]
    const float* cb = (const float*)d_in[1];   // codebook [4096, 512]
    if (in_sizes[0] == KC * DIM) {             // defensive: swap if order differs
        z  = (const float*)d_in[1];
        cb = (const float*)d_in[0];
    }
    float* out = (float*)d_out;                // [z_q_st | k | vq_loss | utilization]

    init_kernel<<<(KC + 255) / 256, 256>>>();
    wnorm_kernel<<<KC / 256, 256>>>(cb);
    xnorm_kernel<<<NROWS / 256, 256>>>(z);
    {
        dim3 blk(32, 8);
        transposeA_kernel<<<dim3(DIM / 32, NROWS / 32), blk>>>(z);
        transposeB_kernel<<<dim3(DIM / 32, KC / 32),   blk>>>(cb);
    }
    vq_argmin_kernel<<<NROWS / BM, 128>>>();
    gather_kernel<<<NROWS, 128>>>(z, cb, out);
    finalize_kernel<<<1, 1024>>>(out);
}

// round 6
// speedup vs baseline: 1.4378x; 1.0649x over previous
#include <cuda_runtime.h>
#include <cstdint>

// Fixed shapes: z_e [16,2048,512] -> N=32768 rows, codebook [4096,512]
#define NROWS 32768
#define DIM   512
#define KC    4096

__device__ float g_wnorm[KC];
__device__ float g_xnorm[NROWS];
__device__ int   g_k[NROWS];
__device__ float g_partial[NROWS];
__device__ int   g_used[KC];
// k-major transposed operands (sanctioned static scratch)
__device__ float g_AT[DIM * NROWS];   // AT[d][m] = z[m][d]      (64 MB)
__device__ float g_BT[DIM * KC];      // BT[d][n] = cb[n][d]     ( 8 MB)

// ---------------------------------------------------------------------------
__global__ void init_kernel() {
    int i = blockIdx.x * blockDim.x + threadIdx.x;
    if (i < KC) g_used[i] = 0;
}

// ---------------------------------------------------------------------------
// Tiled transposes: in[R][512] -> out[512][R]
__global__ void transposeA_kernel(const float* __restrict__ in) {
    __shared__ float tile[32][33];
    int c0 = blockIdx.x * 32, r0 = blockIdx.y * 32;
    #pragma unroll
    for (int i = threadIdx.y; i < 32; i += 8)
        tile[i][threadIdx.x] = in[(size_t)(r0 + i) * DIM + c0 + threadIdx.x];
    __syncthreads();
    #pragma unroll
    for (int i = threadIdx.y; i < 32; i += 8)
        g_AT[(size_t)(c0 + i) * NROWS + r0 + threadIdx.x] = tile[threadIdx.x][i];
}

__global__ void transposeB_kernel(const float* __restrict__ in) {
    __shared__ float tile[32][33];
    int c0 = blockIdx.x * 32, r0 = blockIdx.y * 32;
    #pragma unroll
    for (int i = threadIdx.y; i < 32; i += 8)
        tile[i][threadIdx.x] = in[(size_t)(r0 + i) * DIM + c0 + threadIdx.x];
    __syncthreads();
    #pragma unroll
    for (int i = threadIdx.y; i < 32; i += 8)
        g_BT[(size_t)(c0 + i) * KC + r0 + threadIdx.x] = tile[threadIdx.x][i];
}

// ---------------------------------------------------------------------------
// ||w||^2 / ||x||^2 from the k-major arrays (coalesced): same sequential
// ascending-d scalar chain acc = fl(acc + fl(v*v)) -> bit-identical values.
__global__ void wnorm_kernel() {
    int code = blockIdx.x * blockDim.x + threadIdx.x;
    if (code >= KC) return;
    float acc = 0.f;
    for (int d = 0; d < DIM; d++) {
        float v = g_BT[(size_t)d * KC + code];
        acc = __fadd_rn(acc, __fmul_rn(v, v));
    }
    g_wnorm[code] = acc;
}

__global__ void xnorm_kernel() {
    int row = blockIdx.x * blockDim.x + threadIdx.x;
    if (row >= NROWS) return;
    float acc = 0.f;
    for (int d = 0; d < DIM; d++) {
        float v = g_AT[(size_t)d * NROWS + row];
        acc = __fadd_rn(acc, __fmul_rn(v, v));
    }
    g_xnorm[row] = acc;
}

// ---------------------------------------------------------------------------
// Packed f32x2: each 32-bit half is an independent IEEE fp32 FMA chain.
__device__ __forceinline__ unsigned long long dup2(float a) {
    unsigned long long r;
    asm("mov.b64 %0, {%1, %1};" : "=l"(r) : "f"(a));
    return r;
}
__device__ __forceinline__ void fma2(unsigned long long& d,
                                     unsigned long long a,
                                     unsigned long long b) {
    asm("fma.rn.f32x2 %0, %1, %2, %0;" : "+l"(d) : "l"(a), "l"(b));
}
union U64F2 { unsigned long long u; float2 f; };

__device__ __forceinline__ void cp16(uint32_t smem, const float* g) {
    asm volatile("cp.async.cg.shared.global [%0], [%1], 16;" :: "r"(smem), "l"(g));
}

// ---------------------------------------------------------------------------
// Fused fp32 GEMM + argmin, 3-stage cp.async ring, ONE barrier per stage.
//  - dot per (row,code): single ascending-k FMA chain, bit-identical to all
//    passing rounds (2 chains per fma.rn.f32x2).
//  - score: d = fl( fl(xnorm - fl(2*dot)) + wnorm )
//  - argmin: (value,index) comparator == jnp.argmin first-occurrence,
//    merged across the 16 col-groups by 16-lane warp butterfly (no smem).
// Tile: BM=64 x BN=256, BK=16, 128 threads, 8x16 per thread.
#define BM 64
#define BN 256
#define BK 16
#define TM 8
#define NSTAGE 512              // (KC/BN) * (DIM/BK) = 16 * 32
#define A_STG (BK * BM)         // floats per A stage
#define B_STG (BK * BN)         // floats per B stage
#define SMEM_BYTES (3 * (A_STG + B_STG) * 4)   // 61440

extern __shared__ float dynsmem[];

__global__ void __launch_bounds__(128, 2)
vq_argmin_kernel() {
    float* As = dynsmem;                 // [3][BK][BM]
    float* Bs = dynsmem + 3 * A_STG;     // [3][BK][BN]

    const int tid = threadIdx.x;
    const int tx  = tid & 15;    // col group
    const int ty  = tid >> 4;    // row group (0..7)
    const int rowBase = blockIdx.x * BM;

    // loop-invariant row norms (one per assigned row)
    float xn[TM];
    #pragma unroll
    for (int i = 0; i < TM; i++) xn[i] = g_xnorm[rowBase + ty * TM + i];

    float bestV = 3.4e38f;       // valid on threads with tx < 8 (row ty*8+tx)
    int   bestI = 0x7fffffff;

    auto prefetch = [&](int t) {
        int b  = t % 3;
        int cb = (t >> 5) * BN;
        int dk = (t & 31) * BK;
        #pragma unroll
        for (int u = 0; u < 2; u++) {                 // A: 256 x 16B
            int idx = tid + u * 128;
            int k = idx >> 4, seg = (idx & 15) * 4;
            cp16((uint32_t)__cvta_generic_to_shared(&As[b * A_STG + k * BM + seg]),
                 &g_AT[(size_t)(dk + k) * NROWS + rowBase + seg]);
        }
        #pragma unroll
        for (int u = 0; u < 8; u++) {                 // B: 1024 x 16B
            int idx = tid + u * 128;
            int k = idx >> 6, seg = (idx & 63) * 4;
            cp16((uint32_t)__cvta_generic_to_shared(&Bs[b * B_STG + k * BN + seg]),
                 &g_BT[(size_t)(dk + k) * KC + cb + seg]);
        }
    };

    prefetch(0); asm volatile("cp.async.commit_group;");
    prefetch(1); asm volatile("cp.async.commit_group;");

    int sg = 0;   // current compute stage
    for (int cbase = 0; cbase < KC; cbase += BN) {
        unsigned long long acc[TM][8];
        #pragma unroll
        for (int i = 0; i < TM; i++)
            #pragma unroll
            for (int p = 0; p < 8; p++) acc[i][p] = 0ull;

        for (int dk = 0; dk < DIM; dk += BK) {
            asm volatile("cp.async.wait_group 1;");
            __syncthreads();              // stage sg visible; stage sg-1 compute done
            if (sg + 2 < NSTAGE) prefetch(sg + 2);
            asm volatile("cp.async.commit_group;");

            const float* Ab = &As[(sg % 3) * A_STG];
            const float* Bb = &Bs[(sg % 3) * B_STG];
            #pragma unroll
            for (int kk = 0; kk < BK; kk++) {
                float a[TM];
                *(float4*)&a[0] = *(const float4*)&Ab[kk * BM + ty * TM];
                *(float4*)&a[4] = *(const float4*)&Ab[kk * BM + ty * TM + 4];
                unsigned long long bq[8];
                #pragma unroll
                for (int j = 0; j < 4; j++) {
                    ulonglong2 b = *(const ulonglong2*)&Bb[kk * BN + 4 * (tx + 16 * j)];
                    bq[2 * j]     = b.x;
                    bq[2 * j + 1] = b.y;
                }
                #pragma unroll
                for (int i = 0; i < TM; i++) {
                    unsigned long long ad = dup2(a[i]);
                    #pragma unroll
                    for (int p = 0; p < 8; p++)
                        fma2(acc[i][p], ad, bq[p]);
                }
            }
            sg++;
        }

        // argmin epilogue: per-thread scan (reference rounding order), then
        // 16-lane butterfly merge with (value,index) comparator.
        #pragma unroll
        for (int i = 0; i < TM; i++) {
            float mv = 3.4e38f; int mi = 0x7fffffff;
            #pragma unroll
            for (int j = 0; j < 4; j++) {
                #pragma unroll
                for (int h = 0; h < 2; h++) {
                    U64F2 u; u.u = acc[i][2 * j + h];
                    int c0 = cbase + 4 * (tx + 16 * j) + 2 * h;
                    float av[2] = { u.f.x, u.f.y };
                    #pragma unroll
                    for (int e = 0; e < 2; e++) {
                        int   col = c0 + e;
                        float p   = __fmul_rn(2.0f, av[e]);
                        float q   = __fsub_rn(xn[i], p);
                        float sc  = __fadd_rn(q, g_wnorm[col]);
                        if (sc < mv || (sc == mv && col < mi)) { mv = sc; mi = col; }
                    }
                }
            }
            #pragma unroll
            for (int off = 8; off > 0; off >>= 1) {
                float ov = __shfl_xor_sync(0xffffffffu, mv, off);
                int   oi = __shfl_xor_sync(0xffffffffu, mi, off);
                if (ov < mv || (ov == mv && oi < mi)) { mv = ov; mi = oi; }
            }
            if (tx == i) {
                if (mv < bestV || (mv == bestV && mi < bestI)) { bestV = mv; bestI = mi; }
            }
        }
    }

    if (tx < TM) g_k[rowBase + ty * TM + tx] = bestI;
}

// ---------------------------------------------------------------------------
// Gather z_q, ST output x + (z_q - x) (same fp ops as JAX), loss partials,
// used flags, k as float.
__global__ void gather_kernel(const float* __restrict__ z,
                              const float* __restrict__ cb,
                              float* __restrict__ out) {
    __shared__ float red[128];
    int row = blockIdx.x;
    int t   = threadIdx.x;
    int k   = g_k[row];

    float4 w = reinterpret_cast<const float4*>(cb + (size_t)k   * DIM)[t];
    float4 x = reinterpret_cast<const float4*>(z  + (size_t)row * DIM)[t];

    float4 o;
    o.x = __fadd_rn(x.x, __fsub_rn(w.x, x.x));
    o.y = __fadd_rn(x.y, __fsub_rn(w.y, x.y));
    o.z = __fadd_rn(x.z, __fsub_rn(w.z, x.z));
    o.w = __fadd_rn(x.w, __fsub_rn(w.w, x.w));
    reinterpret_cast<float4*>(out + (size_t)row * DIM)[t] = o;

    float dx = __fsub_rn(x.x, w.x), dy = __fsub_rn(x.y, w.y);
    float dz = __fsub_rn(x.z, w.z), dw = __fsub_rn(x.w, w.w);
    red[t] = dx * dx + dy * dy + dz * dz + dw * dw;
    __syncthreads();
    #pragma unroll
    for (int off = 64; off > 0; off >>= 1) {
        if (t < off) red[t] += red[t + off];
        __syncthreads();
    }
    if (t == 0) {
        g_partial[row] = red[0];
        g_used[k] = 1;
        out[(size_t)NROWS * DIM + row] = (float)k;   // k segment
    }
}

// ---------------------------------------------------------------------------
__global__ void finalize_kernel(float* __restrict__ out) {
    __shared__ double red[1024];
    int t = threadIdx.x;

    double s = 0.0;
    for (int i = t; i < NROWS; i += 1024) s += (double)g_partial[i];
    red[t] = s;
    __syncthreads();
    #pragma unroll
    for (int off = 512; off > 0; off >>= 1) {
        if (t < off) red[t] += red[t + off];
        __syncthreads();
    }
    double lossTotal = red[0];
    __syncthreads();

    double u = 0.0;
    for (int i = t; i < KC; i += 1024) u += (double)g_used[i];
    red[t] = u;
    __syncthreads();
    #pragma unroll
    for (int off = 512; off > 0; off >>= 1) {
        if (t < off) red[t] += red[t + off];
        __syncthreads();
    }

    if (t == 0) {
        size_t base = (size_t)NROWS * DIM + NROWS;
        out[base]     = (float)(0.25 * lossTotal / ((double)NROWS * (double)DIM));
        out[base + 1] = (float)(red[0] / (double)KC);
    }
}

// ---------------------------------------------------------------------------
extern "C" void kernel_launch(void* const* d_in, const int* in_sizes, int n_in,
                              void* d_out, int out_size) {
    const float* z  = (const float*)d_in[0];   // z_e [32768, 512]
    const float* cb = (const float*)d_in[1];   // codebook [4096, 512]
    if (in_sizes[0] == KC * DIM) {             // defensive: swap if order differs
        z  = (const float*)d_in[1];
        cb = (const float*)d_in[0];
    }
    float* out = (float*)d_out;                // [z_q_st | k | vq_loss | utilization]

    cudaFuncSetAttribute(vq_argmin_kernel,
                         cudaFuncAttributeMaxDynamicSharedMemorySize, SMEM_BYTES);

    init_kernel<<<(KC + 255) / 256, 256>>>();
    {
        dim3 blk(32, 8);
        transposeA_kernel<<<dim3(DIM / 32, NROWS / 32), blk>>>(z);
        transposeB_kernel<<<dim3(DIM / 32, KC / 32),   blk>>>(cb);
    }
    wnorm_kernel<<<KC / 256, 256>>>();
    xnorm_kernel<<<NROWS / 256, 256>>>();
    vq_argmin_kernel<<<NROWS / BM, 128, SMEM_BYTES>>>();
    gather_kernel<<<NROWS, 128>>>(z, cb, out);
    finalize_kernel<<<1, 1024>>>(out);
}

// round 7
// speedup vs baseline: 1.5719x; 1.0932x over previous
#include <cuda_runtime.h>
#include <cstdint>

// Fixed shapes: z_e [16,2048,512] -> N=32768 rows, codebook [4096,512]
#define NROWS 32768
#define DIM   512
#define KC    4096

__device__ float g_wnorm[KC];
__device__ float g_xnorm[NROWS];
__device__ float g_partial[NROWS];
__device__ int   g_used[KC];
// per-(chunk,row) partial argmin results
#define NCHUNK 4
__device__ float g_pval[NCHUNK * NROWS];
__device__ int   g_pidx[NCHUNK * NROWS];
// k-major transposed operands (sanctioned static scratch)
__device__ float g_AT[DIM * NROWS];   // AT[d][m] = z[m][d]      (64 MB)
__device__ float g_BT[DIM * KC];      // BT[d][n] = cb[n][d]     ( 8 MB)

// ---------------------------------------------------------------------------
__global__ void init_kernel() {
    int i = blockIdx.x * blockDim.x + threadIdx.x;
    if (i < KC) g_used[i] = 0;
}

// ---------------------------------------------------------------------------
// Tiled transposes: in[R][512] -> out[512][R]
__global__ void transposeA_kernel(const float* __restrict__ in) {
    __shared__ float tile[32][33];
    int c0 = blockIdx.x * 32, r0 = blockIdx.y * 32;
    #pragma unroll
    for (int i = threadIdx.y; i < 32; i += 8)
        tile[i][threadIdx.x] = in[(size_t)(r0 + i) * DIM + c0 + threadIdx.x];
    __syncthreads();
    #pragma unroll
    for (int i = threadIdx.y; i < 32; i += 8)
        g_AT[(size_t)(c0 + i) * NROWS + r0 + threadIdx.x] = tile[threadIdx.x][i];
}

__global__ void transposeB_kernel(const float* __restrict__ in) {
    __shared__ float tile[32][33];
    int c0 = blockIdx.x * 32, r0 = blockIdx.y * 32;
    #pragma unroll
    for (int i = threadIdx.y; i < 32; i += 8)
        tile[i][threadIdx.x] = in[(size_t)(r0 + i) * DIM + c0 + threadIdx.x];
    __syncthreads();
    #pragma unroll
    for (int i = threadIdx.y; i < 32; i += 8)
        g_BT[(size_t)(c0 + i) * KC + r0 + threadIdx.x] = tile[threadIdx.x][i];
}

// ---------------------------------------------------------------------------
// ||w||^2 / ||x||^2 from the k-major arrays (coalesced): same sequential
// ascending-d scalar chain acc = fl(acc + fl(v*v)) -> bit-identical values.
__global__ void wnorm_kernel() {          // 64 blocks x 64 threads: latency spread
    int code = blockIdx.x * blockDim.x + threadIdx.x;
    if (code >= KC) return;
    float acc = 0.f;
    for (int d = 0; d < DIM; d++) {
        float v = g_BT[(size_t)d * KC + code];
        acc = __fadd_rn(acc, __fmul_rn(v, v));
    }
    g_wnorm[code] = acc;
}

__global__ void xnorm_kernel() {
    int row = blockIdx.x * blockDim.x + threadIdx.x;
    if (row >= NROWS) return;
    float acc = 0.f;
    for (int d = 0; d < DIM; d++) {
        float v = g_AT[(size_t)d * NROWS + row];
        acc = __fadd_rn(acc, __fmul_rn(v, v));
    }
    g_xnorm[row] = acc;
}

// ---------------------------------------------------------------------------
// Packed f32x2: each 32-bit half is an independent IEEE fp32 FMA chain.
__device__ __forceinline__ unsigned long long dup2(float a) {
    unsigned long long r;
    asm("mov.b64 %0, {%1, %1};" : "=l"(r) : "f"(a));
    return r;
}
__device__ __forceinline__ void fma2(unsigned long long& d,
                                     unsigned long long a,
                                     unsigned long long b) {
    asm("fma.rn.f32x2 %0, %1, %2, %0;" : "+l"(d) : "l"(a), "l"(b));
}
union U64F2 { unsigned long long u; float2 f; };

__device__ __forceinline__ void cp16(uint32_t smem, const float* g) {
    asm volatile("cp.async.cg.shared.global [%0], [%1], 16;" :: "r"(smem), "l"(g));
}

// ---------------------------------------------------------------------------
// Persistent fused fp32 GEMM + argmin.
// Work = 2048 tiles: 512 row-tiles (BM=64) x 4 code-chunks (1024 codes).
// grid = 304 CTAs (152 SMs x occ2); CTA b does tiles b, b+304, ... (6-7 each)
// -> ~4% tail imbalance instead of ~16% wave quantization.
//  - dot per (row,code): single ascending-k FMA chain, bit-identical to all
//    passing rounds (2 chains per fma.rn.f32x2).
//  - score: d = fl( fl(xnorm - fl(2*dot)) + wnorm )
//  - argmin: (value,index) comparator; per-chunk partials merged in gather
//    over ascending disjoint ranges == jnp.argmin first-occurrence.
#define BM 64
#define BN 256
#define BK 16
#define TM 8
#define NTILES 2048
#define VQ_GRID 304
#define TSTAGES 128             // (1024/BN) * (DIM/BK) = 4 * 32 per tile
#define A_STG (BK * BM)
#define B_STG (BK * BN)
#define SMEM_BYTES (3 * (A_STG + B_STG) * 4)   // 61440

extern __shared__ float dynsmem[];

__global__ void __launch_bounds__(128, 2)
vq_argmin_kernel() {
    float* As = dynsmem;                 // [3][BK][BM]
    float* Bs = dynsmem + 3 * A_STG;     // [3][BK][BN]

    const int tid = threadIdx.x;
    const int tx  = tid & 15;    // col group
    const int ty  = tid >> 4;    // row group (0..7)

    for (int t = blockIdx.x; t < NTILES; t += gridDim.x) {
        const int rowBase = (t >> 2) * BM;
        const int cbase0  = (t & 3) * (KC / NCHUNK);

        float xn[TM];
        #pragma unroll
        for (int i = 0; i < TM; i++) xn[i] = g_xnorm[rowBase + ty * TM + i];

        float bestV = 3.4e38f;   // carried on threads tx<8 (row ty*8+tx)
        int   bestI = 0x7fffffff;

        auto prefetch = [&](int s) {
            int b  = s % 3;
            int cb = cbase0 + (s >> 5) * BN;
            int dk = (s & 31) * BK;
            #pragma unroll
            for (int u = 0; u < 2; u++) {                 // A: 256 x 16B
                int idx = tid + u * 128;
                int k = idx >> 4, seg = (idx & 15) * 4;
                cp16((uint32_t)__cvta_generic_to_shared(&As[b * A_STG + k * BM + seg]),
                     &g_AT[(size_t)(dk + k) * NROWS + rowBase + seg]);
            }
            #pragma unroll
            for (int u = 0; u < 8; u++) {                 // B: 1024 x 16B
                int idx = tid + u * 128;
                int k = idx >> 6, seg = (idx & 63) * 4;
                cp16((uint32_t)__cvta_generic_to_shared(&Bs[b * B_STG + k * BN + seg]),
                     &g_BT[(size_t)(dk + k) * KC + cb + seg]);
            }
        };

        prefetch(0); asm volatile("cp.async.commit_group;");
        prefetch(1); asm volatile("cp.async.commit_group;");

        int sg = 0;
        for (int cb8 = 0; cb8 < 4; cb8++) {
            const int cbase = cbase0 + cb8 * BN;
            unsigned long long acc[TM][8];
            #pragma unroll
            for (int i = 0; i < TM; i++)
                #pragma unroll
                for (int p = 0; p < 8; p++) acc[i][p] = 0ull;

            for (int dk = 0; dk < DIM; dk += BK) {
                asm volatile("cp.async.wait_group 1;");
                __syncthreads();
                if (sg + 2 < TSTAGES) prefetch(sg + 2);
                asm volatile("cp.async.commit_group;");

                const float* Ab = &As[(sg % 3) * A_STG];
                const float* Bb = &Bs[(sg % 3) * B_STG];
                #pragma unroll
                for (int kk = 0; kk < BK; kk++) {
                    float a[TM];
                    *(float4*)&a[0] = *(const float4*)&Ab[kk * BM + ty * TM];
                    *(float4*)&a[4] = *(const float4*)&Ab[kk * BM + ty * TM + 4];
                    unsigned long long bq[8];
                    #pragma unroll
                    for (int j = 0; j < 4; j++) {
                        ulonglong2 b = *(const ulonglong2*)&Bb[kk * BN + 4 * (tx + 16 * j)];
                        bq[2 * j]     = b.x;
                        bq[2 * j + 1] = b.y;
                    }
                    #pragma unroll
                    for (int i = 0; i < TM; i++) {
                        unsigned long long ad = dup2(a[i]);
                        #pragma unroll
                        for (int p = 0; p < 8; p++)
                            fma2(acc[i][p], ad, bq[p]);
                    }
                }
                sg++;
            }

            // argmin epilogue: per-thread scan (reference rounding order),
            // 16-lane butterfly with (value,index) comparator.
            #pragma unroll
            for (int i = 0; i < TM; i++) {
                float mv = 3.4e38f; int mi = 0x7fffffff;
                #pragma unroll
                for (int j = 0; j < 4; j++) {
                    #pragma unroll
                    for (int h = 0; h < 2; h++) {
                        U64F2 u; u.u = acc[i][2 * j + h];
                        int c0 = cbase + 4 * (tx + 16 * j) + 2 * h;
                        float av[2] = { u.f.x, u.f.y };
                        #pragma unroll
                        for (int e = 0; e < 2; e++) {
                            int   col = c0 + e;
                            float p   = __fmul_rn(2.0f, av[e]);
                            float q   = __fsub_rn(xn[i], p);
                            float sc  = __fadd_rn(q, g_wnorm[col]);
                            if (sc < mv || (sc == mv && col < mi)) { mv = sc; mi = col; }
                        }
                    }
                }
                #pragma unroll
                for (int off = 8; off > 0; off >>= 1) {
                    float ov = __shfl_xor_sync(0xffffffffu, mv, off);
                    int   oi = __shfl_xor_sync(0xffffffffu, mi, off);
                    if (ov < mv || (ov == mv && oi < mi)) { mv = ov; mi = oi; }
                }
                if (tx == i) {
                    if (mv < bestV || (mv == bestV && mi < bestI)) { bestV = mv; bestI = mi; }
                }
            }
        }

        if (tx < TM) {
            int r = rowBase + ty * TM + tx;
            g_pval[(t & 3) * NROWS + r] = bestV;
            g_pidx[(t & 3) * NROWS + r] = bestI;
        }
        __syncthreads();   // drain: next tile's prefetch reuses smem buffers
    }
}

// ---------------------------------------------------------------------------
// Merge per-chunk partials (ascending disjoint ranges -> first-occurrence),
// gather z_q, ST output x + (z_q - x), loss partials, used flags, k as float.
__global__ void gather_kernel(const float* __restrict__ z,
                              const float* __restrict__ cb,
                              float* __restrict__ out) {
    __shared__ float red[128];
    int row = blockIdx.x;
    int t   = threadIdx.x;

    float bv = 3.4e38f; int k = 0x7fffffff;
    #pragma unroll
    for (int c = 0; c < NCHUNK; c++) {
        float v = g_pval[c * NROWS + row];
        int   i = g_pidx[c * NROWS + row];
        if (v < bv || (v == bv && i < k)) { bv = v; k = i; }
    }

    float4 w = reinterpret_cast<const float4*>(cb + (size_t)k   * DIM)[t];
    float4 x = reinterpret_cast<const float4*>(z  + (size_t)row * DIM)[t];

    float4 o;
    o.x = __fadd_rn(x.x, __fsub_rn(w.x, x.x));
    o.y = __fadd_rn(x.y, __fsub_rn(w.y, x.y));
    o.z = __fadd_rn(x.z, __fsub_rn(w.z, x.z));
    o.w = __fadd_rn(x.w, __fsub_rn(w.w, x.w));
    reinterpret_cast<float4*>(out + (size_t)row * DIM)[t] = o;

    float dx = __fsub_rn(x.x, w.x), dy = __fsub_rn(x.y, w.y);
    float dz = __fsub_rn(x.z, w.z), dw = __fsub_rn(x.w, w.w);
    red[t] = dx * dx + dy * dy + dz * dz + dw * dw;
    __syncthreads();
    #pragma unroll
    for (int off = 64; off > 0; off >>= 1) {
        if (t < off) red[t] += red[t + off];
        __syncthreads();
    }
    if (t == 0) {
        g_partial[row] = red[0];
        g_used[k] = 1;
        out[(size_t)NROWS * DIM + row] = (float)k;   // k segment
    }
}

// ---------------------------------------------------------------------------
__global__ void finalize_kernel(float* __restrict__ out) {
    __shared__ double red[1024];
    int t = threadIdx.x;

    double s = 0.0;
    for (int i = t; i < NROWS; i += 1024) s += (double)g_partial[i];
    red[t] = s;
    __syncthreads();
    #pragma unroll
    for (int off = 512; off > 0; off >>= 1) {
        if (t < off) red[t] += red[t + off];
        __syncthreads();
    }
    double lossTotal = red[0];
    __syncthreads();

    double u = 0.0;
    for (int i = t; i < KC; i += 1024) u += (double)g_used[i];
    red[t] = u;
    __syncthreads();
    #pragma unroll
    for (int off = 512; off > 0; off >>= 1) {
        if (t < off) red[t] += red[t + off];
        __syncthreads();
    }

    if (t == 0) {
        size_t base = (size_t)NROWS * DIM + NROWS;
        out[base]     = (float)(0.25 * lossTotal / ((double)NROWS * (double)DIM));
        out[base + 1] = (float)(red[0] / (double)KC);
    }
}

// ---------------------------------------------------------------------------
extern "C" void kernel_launch(void* const* d_in, const int* in_sizes, int n_in,
                              void* d_out, int out_size) {
    const float* z  = (const float*)d_in[0];   // z_e [32768, 512]
    const float* cb = (const float*)d_in[1];   // codebook [4096, 512]
    if (in_sizes[0] == KC * DIM) {             // defensive: swap if order differs
        z  = (const float*)d_in[1];
        cb = (const float*)d_in[0];
    }
    float* out = (float*)d_out;                // [z_q_st | k | vq_loss | utilization]

    cudaFuncSetAttribute(vq_argmin_kernel,
                         cudaFuncAttributeMaxDynamicSharedMemorySize, SMEM_BYTES);

    init_kernel<<<(KC + 255) / 256, 256>>>();
    {
        dim3 blk(32, 8);
        transposeA_kernel<<<dim3(DIM / 32, NROWS / 32), blk>>>(z);
        transposeB_kernel<<<dim3(DIM / 32, KC / 32),   blk>>>(cb);
    }
    wnorm_kernel<<<64, 64>>>();
    xnorm_kernel<<<NROWS / 128, 128>>>();
    vq_argmin_kernel<<<VQ_GRID, 128, SMEM_BYTES>>>();
    gather_kernel<<<NROWS, 128>>>(z, cb, out);
    finalize_kernel<<<1, 1024>>>(out);
}

// round 8
// speedup vs baseline: 1.5751x; 1.0021x over previous
#include <cuda_runtime.h>
#include <cstdint>

// Fixed shapes: z_e [16,2048,512] -> N=32768 rows, codebook [4096,512]
#define NROWS 32768
#define DIM   512
#define KC    4096

__device__ float g_wnorm[KC];
__device__ float g_xnorm[NROWS];
__device__ float g_partial[NROWS];
__device__ int   g_used[KC];
// per-(chunk,row) partial argmin results
#define NCHUNK 4
__device__ float g_pval[NCHUNK * NROWS];
__device__ int   g_pidx[NCHUNK * NROWS];
// k-major transposed operands (sanctioned static scratch)
__device__ float g_AT[DIM * NROWS];   // AT[d][m] = z[m][d]      (64 MB)
__device__ float g_BT[DIM * KC];      // BT[d][n] = cb[n][d]     ( 8 MB)

// ---------------------------------------------------------------------------
__global__ void init_kernel() {
    int i = blockIdx.x * blockDim.x + threadIdx.x;
    if (i < KC) g_used[i] = 0;
}

// ---------------------------------------------------------------------------
// Tiled transposes: in[R][512] -> out[512][R]
__global__ void transposeA_kernel(const float* __restrict__ in) {
    __shared__ float tile[32][33];
    int c0 = blockIdx.x * 32, r0 = blockIdx.y * 32;
    #pragma unroll
    for (int i = threadIdx.y; i < 32; i += 8)
        tile[i][threadIdx.x] = in[(size_t)(r0 + i) * DIM + c0 + threadIdx.x];
    __syncthreads();
    #pragma unroll
    for (int i = threadIdx.y; i < 32; i += 8)
        g_AT[(size_t)(c0 + i) * NROWS + r0 + threadIdx.x] = tile[threadIdx.x][i];
}

__global__ void transposeB_kernel(const float* __restrict__ in) {
    __shared__ float tile[32][33];
    int c0 = blockIdx.x * 32, r0 = blockIdx.y * 32;
    #pragma unroll
    for (int i = threadIdx.y; i < 32; i += 8)
        tile[i][threadIdx.x] = in[(size_t)(r0 + i) * DIM + c0 + threadIdx.x];
    __syncthreads();
    #pragma unroll
    for (int i = threadIdx.y; i < 32; i += 8)
        g_BT[(size_t)(c0 + i) * KC + r0 + threadIdx.x] = tile[threadIdx.x][i];
}

// ---------------------------------------------------------------------------
// ||w||^2 / ||x||^2 from the k-major arrays (coalesced): same sequential
// ascending-d scalar chain acc = fl(acc + fl(v*v)) -> bit-identical values.
__global__ void wnorm_kernel() {          // 64 blocks x 64 threads: latency spread
    int code = blockIdx.x * blockDim.x + threadIdx.x;
    if (code >= KC) return;
    float acc = 0.f;
    for (int d = 0; d < DIM; d++) {
        float v = g_BT[(size_t)d * KC + code];
        acc = __fadd_rn(acc, __fmul_rn(v, v));
    }
    g_wnorm[code] = acc;
}

__global__ void xnorm_kernel() {
    int row = blockIdx.x * blockDim.x + threadIdx.x;
    if (row >= NROWS) return;
    float acc = 0.f;
    for (int d = 0; d < DIM; d++) {
        float v = g_AT[(size_t)d * NROWS + row];
        acc = __fadd_rn(acc, __fmul_rn(v, v));
    }
    g_xnorm[row] = acc;
}

// ---------------------------------------------------------------------------
// Packed f32x2: each 32-bit half is an independent IEEE fp32 FMA chain.
__device__ __forceinline__ unsigned long long dup2(float a) {
    unsigned long long r;
    asm("mov.b64 %0, {%1, %1};" : "=l"(r) : "f"(a));
    return r;
}
__device__ __forceinline__ void fma2(unsigned long long& d,
                                     unsigned long long a,
                                     unsigned long long b) {
    asm("fma.rn.f32x2 %0, %1, %2, %0;" : "+l"(d) : "l"(a), "l"(b));
}
union U64F2 { unsigned long long u; float2 f; };

__device__ __forceinline__ void cp16(uint32_t smem, const float* g) {
    asm volatile("cp.async.cg.shared.global [%0], [%1], 16;" :: "r"(smem), "l"(g));
}

// ---------------------------------------------------------------------------
// Persistent fused fp32 GEMM + argmin.
// Work = 2048 tiles: 512 row-tiles (BM=64) x 4 code-chunks (1024 codes).
// grid = 304 CTAs (152 SMs x occ2); CTA b does tiles b, b+304, ... (6-7 each)
// -> ~4% tail imbalance instead of ~16% wave quantization.
//  - dot per (row,code): single ascending-k FMA chain, bit-identical to all
//    passing rounds (2 chains per fma.rn.f32x2).
//  - score: d = fl( fl(xnorm - fl(2*dot)) + wnorm )
//  - argmin: (value,index) comparator; per-chunk partials merged in gather
//    over ascending disjoint ranges == jnp.argmin first-occurrence.
#define BM 64
#define BN 256
#define BK 16
#define TM 8
#define NTILES 2048
#define VQ_GRID 304
#define TSTAGES 128             // (1024/BN) * (DIM/BK) = 4 * 32 per tile
#define A_STG (BK * BM)
#define B_STG (BK * BN)
#define SMEM_BYTES (3 * (A_STG + B_STG) * 4)   // 61440

extern __shared__ float dynsmem[];

__global__ void __launch_bounds__(128, 2)
vq_argmin_kernel() {
    float* As = dynsmem;                 // [3][BK][BM]
    float* Bs = dynsmem + 3 * A_STG;     // [3][BK][BN]

    const int tid = threadIdx.x;
    const int tx  = tid & 15;    // col group
    const int ty  = tid >> 4;    // row group (0..7)

    for (int t = blockIdx.x; t < NTILES; t += gridDim.x) {
        const int rowBase = (t >> 2) * BM;
        const int cbase0  = (t & 3) * (KC / NCHUNK);

        float xn[TM];
        #pragma unroll
        for (int i = 0; i < TM; i++) xn[i] = g_xnorm[rowBase + ty * TM + i];

        float bestV = 3.4e38f;   // carried on threads tx<8 (row ty*8+tx)
        int   bestI = 0x7fffffff;

        auto prefetch = [&](int s) {
            int b  = s % 3;
            int cb = cbase0 + (s >> 5) * BN;
            int dk = (s & 31) * BK;
            #pragma unroll
            for (int u = 0; u < 2; u++) {                 // A: 256 x 16B
                int idx = tid + u * 128;
                int k = idx >> 4, seg = (idx & 15) * 4;
                cp16((uint32_t)__cvta_generic_to_shared(&As[b * A_STG + k * BM + seg]),
                     &g_AT[(size_t)(dk + k) * NROWS + rowBase + seg]);
            }
            #pragma unroll
            for (int u = 0; u < 8; u++) {                 // B: 1024 x 16B
                int idx = tid + u * 128;
                int k = idx >> 6, seg = (idx & 63) * 4;
                cp16((uint32_t)__cvta_generic_to_shared(&Bs[b * B_STG + k * BN + seg]),
                     &g_BT[(size_t)(dk + k) * KC + cb + seg]);
            }
        };

        prefetch(0); asm volatile("cp.async.commit_group;");
        prefetch(1); asm volatile("cp.async.commit_group;");

        int sg = 0;
        for (int cb8 = 0; cb8 < 4; cb8++) {
            const int cbase = cbase0 + cb8 * BN;
            unsigned long long acc[TM][8];
            #pragma unroll
            for (int i = 0; i < TM; i++)
                #pragma unroll
                for (int p = 0; p < 8; p++) acc[i][p] = 0ull;

            for (int dk = 0; dk < DIM; dk += BK) {
                asm volatile("cp.async.wait_group 1;");
                __syncthreads();
                if (sg + 2 < TSTAGES) prefetch(sg + 2);
                asm volatile("cp.async.commit_group;");

                const float* Ab = &As[(sg % 3) * A_STG];
                const float* Bb = &Bs[(sg % 3) * B_STG];
                #pragma unroll
                for (int kk = 0; kk < BK; kk++) {
                    float a[TM];
                    *(float4*)&a[0] = *(const float4*)&Ab[kk * BM + ty * TM];
                    *(float4*)&a[4] = *(const float4*)&Ab[kk * BM + ty * TM + 4];
                    unsigned long long bq[8];
                    #pragma unroll
                    for (int j = 0; j < 4; j++) {
                        ulonglong2 b = *(const ulonglong2*)&Bb[kk * BN + 4 * (tx + 16 * j)];
                        bq[2 * j]     = b.x;
                        bq[2 * j + 1] = b.y;
                    }
                    #pragma unroll
                    for (int i = 0; i < TM; i++) {
                        unsigned long long ad = dup2(a[i]);
                        #pragma unroll
                        for (int p = 0; p < 8; p++)
                            fma2(acc[i][p], ad, bq[p]);
                    }
                }
                sg++;
            }

            // argmin epilogue: per-thread scan (reference rounding order),
            // 16-lane butterfly with (value,index) comparator.
            #pragma unroll
            for (int i = 0; i < TM; i++) {
                float mv = 3.4e38f; int mi = 0x7fffffff;
                #pragma unroll
                for (int j = 0; j < 4; j++) {
                    #pragma unroll
                    for (int h = 0; h < 2; h++) {
                        U64F2 u; u.u = acc[i][2 * j + h];
                        int c0 = cbase + 4 * (tx + 16 * j) + 2 * h;
                        float av[2] = { u.f.x, u.f.y };
                        #pragma unroll
                        for (int e = 0; e < 2; e++) {
                            int   col = c0 + e;
                            float p   = __fmul_rn(2.0f, av[e]);
                            float q   = __fsub_rn(xn[i], p);
                            float sc  = __fadd_rn(q, g_wnorm[col]);
                            if (sc < mv || (sc == mv && col < mi)) { mv = sc; mi = col; }
                        }
                    }
                }
                #pragma unroll
                for (int off = 8; off > 0; off >>= 1) {
                    float ov = __shfl_xor_sync(0xffffffffu, mv, off);
                    int   oi = __shfl_xor_sync(0xffffffffu, mi, off);
                    if (ov < mv || (ov == mv && oi < mi)) { mv = ov; mi = oi; }
                }
                if (tx == i) {
                    if (mv < bestV || (mv == bestV && mi < bestI)) { bestV = mv; bestI = mi; }
                }
            }
        }

        if (tx < TM) {
            int r = rowBase + ty * TM + tx;
            g_pval[(t & 3) * NROWS + r] = bestV;
            g_pidx[(t & 3) * NROWS + r] = bestI;
        }
        __syncthreads();   // drain: next tile's prefetch reuses smem buffers
    }
}

// ---------------------------------------------------------------------------
// Merge per-chunk partials (ascending disjoint ranges -> first-occurrence),
// gather z_q, ST output x + (z_q - x), loss partials, used flags, k as float.
__global__ void gather_kernel(const float* __restrict__ z,
                              const float* __restrict__ cb,
                              float* __restrict__ out) {
    __shared__ float red[128];
    int row = blockIdx.x;
    int t   = threadIdx.x;

    float bv = 3.4e38f; int k = 0x7fffffff;
    #pragma unroll
    for (int c = 0; c < NCHUNK; c++) {
        float v = g_pval[c * NROWS + row];
        int   i = g_pidx[c * NROWS + row];
        if (v < bv || (v == bv && i < k)) { bv = v; k = i; }
    }

    float4 w = reinterpret_cast<const float4*>(cb + (size_t)k   * DIM)[t];
    float4 x = reinterpret_cast<const float4*>(z  + (size_t)row * DIM)[t];

    float4 o;
    o.x = __fadd_rn(x.x, __fsub_rn(w.x, x.x));
    o.y = __fadd_rn(x.y, __fsub_rn(w.y, x.y));
    o.z = __fadd_rn(x.z, __fsub_rn(w.z, x.z));
    o.w = __fadd_rn(x.w, __fsub_rn(w.w, x.w));
    reinterpret_cast<float4*>(out + (size_t)row * DIM)[t] = o;

    float dx = __fsub_rn(x.x, w.x), dy = __fsub_rn(x.y, w.y);
    float dz = __fsub_rn(x.z, w.z), dw = __fsub_rn(x.w, w.w);
    red[t] = dx * dx + dy * dy + dz * dz + dw * dw;
    __syncthreads();
    #pragma unroll
    for (int off = 64; off > 0; off >>= 1) {
        if (t < off) red[t] += red[t + off];
        __syncthreads();
    }
    if (t == 0) {
        g_partial[row] = red[0];
        g_used[k] = 1;
        out[(size_t)NROWS * DIM + row] = (float)k;   // k segment
    }
}

// ---------------------------------------------------------------------------
__global__ void finalize_kernel(float* __restrict__ out) {
    __shared__ double red[1024];
    int t = threadIdx.x;

    double s = 0.0;
    for (int i = t; i < NROWS; i += 1024) s += (double)g_partial[i];
    red[t] = s;
    __syncthreads();
    #pragma unroll
    for (int off = 512; off > 0; off >>= 1) {
        if (t < off) red[t] += red[t + off];
        __syncthreads();
    }
    double lossTotal = red[0];
    __syncthreads();

    double u = 0.0;
    for (int i = t; i < KC; i += 1024) u += (double)g_used[i];
    red[t] = u;
    __syncthreads();
    #pragma unroll
    for (int off = 512; off > 0; off >>= 1) {
        if (t < off) red[t] += red[t + off];
        __syncthreads();
    }

    if (t == 0) {
        size_t base = (size_t)NROWS * DIM + NROWS;
        out[base]     = (float)(0.25 * lossTotal / ((double)NROWS * (double)DIM));
        out[base + 1] = (float)(red[0] / (double)KC);
    }
}

// ---------------------------------------------------------------------------
extern "C" void kernel_launch(void* const* d_in, const int* in_sizes, int n_in,
                              void* d_out, int out_size) {
    const float* z  = (const float*)d_in[0];   // z_e [32768, 512]
    const float* cb = (const float*)d_in[1];   // codebook [4096, 512]
    if (in_sizes[0] == KC * DIM) {             // defensive: swap if order differs
        z  = (const float*)d_in[1];
        cb = (const float*)d_in[0];
    }
    float* out = (float*)d_out;                // [z_q_st | k | vq_loss | utilization]

    cudaFuncSetAttribute(vq_argmin_kernel,
                         cudaFuncAttributeMaxDynamicSharedMemorySize, SMEM_BYTES);

    init_kernel<<<(KC + 255) / 256, 256>>>();
    {
        dim3 blk(32, 8);
        transposeA_kernel<<<dim3(DIM / 32, NROWS / 32), blk>>>(z);
        transposeB_kernel<<<dim3(DIM / 32, KC / 32),   blk>>>(cb);
    }
    wnorm_kernel<<<64, 64>>>();
    xnorm_kernel<<<NROWS / 128, 128>>>();
    vq_argmin_kernel<<<VQ_GRID, 128, SMEM_BYTES>>>();
    gather_kernel<<<NROWS, 128>>>(z, cb, out);
    finalize_kernel<<<1, 1024>>>(out);
}